// round 13
// baseline (speedup 1.0000x reference)
#include <cuda_runtime.h>
#include <cuda_fp16.h>
#include <math.h>
#include <stdint.h>

// ---------------- problem constants ----------------
#define L        1024
#define DMODEL   1024
#define DINNER   2048
#define NH       32
#define HD       64
#define CONVDIM  2176           // DINNER + 2*G*N
#define DINPROJ  4256           // 2*DINNER + 2*G*N + NH
#define DINPROJ_PAD 4352        // 34 * 128
#define OFF_Z    0
#define OFF_XBC  2048
#define OFF_B    2048
#define OFF_DT   4224
#define EPSF     1e-5f

// ---------------- scratch (device globals; no allocs allowed) ----------------
__device__ float g_zx_f[L * DINPROJ];
__device__ float g_zx_b[L * DINPROJ];
__device__ float g_xbc_f[L * CONVDIM];
__device__ float g_xbc_b[L * CONVDIM];
__device__ float g_dt_f[L * NH];
__device__ float g_dt_b[L * NH];
__device__ float g_dA_f[L * NH];
__device__ float g_dA_b[L * NH];
__device__ float g_y_f[L * DINNER];
__device__ float g_y_b[L * DINNER];

// fp16 operands
__device__ __half g_u16[L * DMODEL];
__device__ __half g_win16_f[DINPROJ_PAD * DMODEL];
__device__ __half g_win16_b[DINPROJ_PAD * DMODEL];
__device__ __half g_wout16_f[DMODEL * DINNER];
__device__ __half g_wout16_b[DMODEL * DINNER];
__device__ __half g_wfin16[DMODEL * (2 * DMODEL)];
__device__ __half g_y16_f[L * DINNER];
__device__ __half g_y16_b[L * DINNER];
__device__ __half g_f16[L * (2 * DMODEL)];

__device__ __forceinline__ float siluf(float x) { return x / (1.f + expf(-x)); }

// ---------------- PTX helpers ----------------
__device__ __forceinline__ uint32_t smem_u32(const void* p) {
    uint32_t a;
    asm("{ .reg .u64 t; cvta.to.shared.u64 t, %1; cvt.u32.u64 %0, t; }" : "=r"(a) : "l"(p));
    return a;
}
__device__ __forceinline__ void cpa16(uint32_t dst, const void* src) {
    asm volatile("cp.async.cg.shared.global [%0], [%1], 16;" :: "r"(dst), "l"(src));
}
__device__ __forceinline__ void cpa4(uint32_t dst, const void* src) {
    asm volatile("cp.async.ca.shared.global [%0], [%1], 4;" :: "r"(dst), "l"(src));
}
#define CP_COMMIT asm volatile("cp.async.commit_group;" ::: "memory")
#define CP_WAIT(n) asm volatile("cp.async.wait_group %0;" :: "n"(n) : "memory")

__device__ __forceinline__ void ldm_x4(uint32_t a[4], uint32_t addr) {
    asm volatile("ldmatrix.sync.aligned.m8n8.x4.shared.b16 {%0,%1,%2,%3}, [%4];"
        : "=r"(a[0]), "=r"(a[1]), "=r"(a[2]), "=r"(a[3]) : "r"(addr));
}
__device__ __forceinline__ void mma_f16(float c[4], const uint32_t a[4], uint32_t b0, uint32_t b1) {
    asm volatile("mma.sync.aligned.m16n8k16.row.col.f32.f16.f16.f32 "
        "{%0,%1,%2,%3}, {%4,%5,%6,%7}, {%8,%9}, {%0,%1,%2,%3};"
        : "+f"(c[0]), "+f"(c[1]), "+f"(c[2]), "+f"(c[3])
        : "r"(a[0]), "r"(a[1]), "r"(a[2]), "r"(a[3]), "r"(b0), "r"(b1));
}
__device__ __forceinline__ uint32_t pack_h2(__half a, __half b) {
    __half2 t(a, b);
    return *reinterpret_cast<uint32_t*>(&t);
}

// ---------------- GEMM argument bundle ----------------
struct GArgs {
    const __half *A0, *A1, *W0, *W1;
    float *C0, *C1;        // EPI=0
    __half *E;             // EPI=1 (silu -> f16 concat buffer, row stride 2048)
    int N, K;
    int flip0, flip1;      // epilogue row flips per z
};

// ================= Unified GEMM: BM=128, BK=64, 256 threads / 8 warps, 2 CTAs/SM =================
// BN=128: warp tile 32x64. BN=64: warp tile 32x32. fp16 single-term, fp32 acc.
// 3-stage cp.async, one __syncthreads per BK=64 chunk. Swizzle: 16B chunk ch ^= (row & 7).
// Simple inner loop (R11 form): B group loaded and consumed immediately -> low live regs, no spills.
template <int BN, int EPI>
__global__ void __launch_bounds__(256, 2) gemm_k(GArgs a)
{
    constexpr int WN = BN / 2;
    constexpr int NT = WN / 8;
    constexpr int NG = WN / 16;
    constexpr int STAGE = 16384 + BN * 128;
    extern __shared__ __align__(128) char smem[];
    const uint32_t sb = smem_u32(smem);
    const int tid = threadIdx.x;
    const int lane = tid & 31;
    const int wid = tid >> 5;
    const int z = blockIdx.z;
    const int bm = blockIdx.y * 128;
    const int bn = blockIdx.x * BN;
    const int m0w = (wid >> 1) * 32;
    const int n0w = (wid & 1) * WN;
    const int N = a.N, K = a.K;

    const __half* A = z ? a.A1 : a.A0;
    const __half* W = z ? a.W1 : a.W0;
    const bool flip = z ? (a.flip1 != 0) : (a.flip0 != 0);

    float acc[2][NT][4];
#pragma unroll
    for (int i = 0; i < 2; i++)
#pragma unroll
        for (int j = 0; j < NT; j++)
#pragma unroll
            for (int q = 0; q < 4; q++) acc[i][j][q] = 0.f;

    auto load_stage = [&](int s, int k0) {
        const uint32_t base = sb + s * STAGE;
#pragma unroll
        for (int it = 0; it < 4; it++) {
            const int q = tid + it * 256;
            const int r = q >> 3, c = q & 7;
            const uint32_t sw = r * 128 + ((uint32_t)(c ^ (r & 7)) << 4);
            cpa16(base + sw, A + (size_t)(bm + r) * K + k0 + c * 8);
        }
#pragma unroll
        for (int it = 0; it < BN / 32; it++) {
            const int q = tid + it * 256;
            const int r = q >> 3, c = q & 7;
            const uint32_t sw = r * 128 + ((uint32_t)(c ^ (r & 7)) << 4);
            cpa16(base + 16384 + sw, W + (size_t)(bn + r) * K + k0 + c * 8);
        }
    };

    const int NC = K >> 6;
    load_stage(0, 0);
    CP_COMMIT;
    load_stage(1, 64);
    CP_COMMIT;

    int cs = 0;
    for (int i = 0; i < NC; i++) {
        if (i + 1 < NC) { CP_WAIT(1); } else { CP_WAIT(0); }
        __syncthreads();
        if (i + 2 < NC) {
            int ps = cs + 2; if (ps >= 3) ps -= 3;
            load_stage(ps, (i + 2) << 6);
            CP_COMMIT;
        }
        const uint32_t base = sb + cs * STAGE;
#pragma unroll
        for (int ks = 0; ks < 4; ks++) {
            const int c0 = ks * 2;
            uint32_t af[2][4];
#pragma unroll
            for (int ii = 0; ii < 2; ii++) {
                const int row = m0w + ii * 16 + (lane & 15);
                const int ch = c0 + (lane >> 4);
                ldm_x4(af[ii], base + row * 128 + (uint32_t)((ch ^ (row & 7)) << 4));
            }
#pragma unroll
            for (int j = 0; j < NG; j++) {
                uint32_t bw[4];
                const int row = n0w + j * 16 + ((lane >> 4) << 3) + (lane & 7);
                const int ch = c0 + ((lane >> 3) & 1);
                ldm_x4(bw, base + 16384 + row * 128 + (uint32_t)((ch ^ (row & 7)) << 4));
                mma_f16(acc[0][2 * j],     af[0], bw[0], bw[1]);
                mma_f16(acc[0][2 * j + 1], af[0], bw[2], bw[3]);
                mma_f16(acc[1][2 * j],     af[1], bw[0], bw[1]);
                mma_f16(acc[1][2 * j + 1], af[1], bw[2], bw[3]);
            }
        }
        cs++; if (cs >= 3) cs = 0;
    }

    if (EPI == 0) {
        float* C = z ? a.C1 : a.C0;
#pragma unroll
        for (int ii = 0; ii < 2; ii++) {
            const int gr = bm + m0w + ii * 16 + (lane >> 2);
            const int r0 = flip ? (1023 - gr) : gr;
            const int r1 = flip ? (1023 - (gr + 8)) : (gr + 8);
#pragma unroll
            for (int jj = 0; jj < NT; jj++) {
                const int gc = bn + n0w + jj * 8 + (lane & 3) * 2;
                if (gc < N) {
                    *reinterpret_cast<float2*>(&C[(size_t)r0 * N + gc]) = make_float2(acc[ii][jj][0], acc[ii][jj][1]);
                    *reinterpret_cast<float2*>(&C[(size_t)r1 * N + gc]) = make_float2(acc[ii][jj][2], acc[ii][jj][3]);
                }
            }
        }
    } else {
        const int colOff = z * 1024;
#pragma unroll
        for (int ii = 0; ii < 2; ii++) {
            const int gr = bm + m0w + ii * 16 + (lane >> 2);
            const int r0 = flip ? (1023 - gr) : gr;
            const int r1 = flip ? (1023 - (gr + 8)) : (gr + 8);
#pragma unroll
            for (int jj = 0; jj < NT; jj++) {
                const int gc = colOff + bn + n0w + jj * 8 + (lane & 3) * 2;
                const float v0 = siluf(acc[ii][jj][0]);
                const float v1 = siluf(acc[ii][jj][1]);
                const float v2 = siluf(acc[ii][jj][2]);
                const float v3 = siluf(acc[ii][jj][3]);
                *reinterpret_cast<uint32_t*>(&a.E[(size_t)r0 * 2048 + gc]) = pack_h2(__float2half(v0), __float2half(v1));
                *reinterpret_cast<uint32_t*>(&a.E[(size_t)r1 * 2048 + gc]) = pack_h2(__float2half(v2), __float2half(v3));
            }
        }
    }
}

// ---------------- flat f32 -> f16 convert, grid-stride, 2-way z ----------------
__global__ void cvtf_kernel(const float* __restrict__ s0, const float* __restrict__ s1,
                            __half* __restrict__ d0, __half* __restrict__ d1,
                            size_t n)
{
    const float* s = blockIdx.z ? s1 : s0;
    __half* d = blockIdx.z ? d1 : d0;
    const size_t stride = (size_t)gridDim.x * blockDim.x * 4;
    for (size_t i = ((size_t)blockIdx.x * blockDim.x + threadIdx.x) * 4; i < n; i += stride) {
        float4 v = *reinterpret_cast<const float4*>(s + i);
        *reinterpret_cast<uint2*>(d + i) =
            make_uint2(pack_h2(__float2half(v.x), __float2half(v.y)),
                       pack_h2(__float2half(v.z), __float2half(v.w)));
    }
}

// ---------------- flat f32 -> f16 convert, grid-stride, 3-way z ----------------
__global__ void cvtf3_kernel(const float* __restrict__ s0, const float* __restrict__ s1,
                             const float* __restrict__ s2,
                             __half* __restrict__ d0, __half* __restrict__ d1,
                             __half* __restrict__ d2, size_t n)
{
    const float* s = (blockIdx.z == 0) ? s0 : (blockIdx.z == 1) ? s1 : s2;
    __half* d = (blockIdx.z == 0) ? d0 : (blockIdx.z == 1) ? d1 : d2;
    const size_t stride = (size_t)gridDim.x * blockDim.x * 4;
    for (size_t i = ((size_t)blockIdx.x * blockDim.x + threadIdx.x) * 4; i < n; i += stride) {
        float4 v = *reinterpret_cast<const float4*>(s + i);
        *reinterpret_cast<uint2*>(d + i) =
            make_uint2(pack_h2(__float2half(v.x), __float2half(v.y)),
                       pack_h2(__float2half(v.z), __float2half(v.w)));
    }
}

// ---------------- depthwise causal conv (width 4) + SiLU + dt/dA tail, z-batched ----------------
__global__ void conv_dt_kernel(const float* __restrict__ zx0, const float* __restrict__ zx1,
                               const float* __restrict__ cw0, const float* __restrict__ cw1,
                               const float* __restrict__ cb0, const float* __restrict__ cb1,
                               const float* __restrict__ db0, const float* __restrict__ db1,
                               const float* __restrict__ al0, const float* __restrict__ al1,
                               float* __restrict__ out0, float* __restrict__ out1,
                               float* __restrict__ dt0, float* __restrict__ dt1,
                               float* __restrict__ dA0, float* __restrict__ dA1)
{
    const int z = blockIdx.y;
    const float* zx = z ? zx1 : zx0;
    const int idx = blockIdx.x * blockDim.x + threadIdx.x;
    if (idx < L * CONVDIM) {
        const float* cw = z ? cw1 : cw0;
        const float* cb = z ? cb1 : cb0;
        float* out = z ? out1 : out0;
        const int t = idx / CONVDIM;
        const int c = idx - t * CONVDIM;
        float acc = cb[c];
#pragma unroll
        for (int k = 0; k < 4; k++) {
            const int tt = t - 3 + k;
            if (tt >= 0)
                acc = fmaf(zx[(size_t)tt * DINPROJ + OFF_XBC + c], cw[c * 4 + k], acc);
        }
        out[(size_t)t * CONVDIM + c] = siluf(acc);
    } else {
        const int j = idx - L * CONVDIM;
        if (j < L * NH) {
            const float* dt_bias = z ? db1 : db0;
            const float* A_log = z ? al1 : al0;
            float* dt_out = z ? dt1 : dt0;
            float* dA_out = z ? dA1 : dA0;
            const int h = j & (NH - 1);
            const float v = zx[(size_t)(j >> 5) * DINPROJ + OFF_DT + h] + dt_bias[h];
            const float sp = (v > 20.f) ? v : log1pf(expf(v));
            dt_out[j] = sp;
            dA_out[j] = expf(sp * (-expf(A_log[h])));
        }
    }
}

// ---------------- SSM scan, cp.async double-buffered staging, z-batched ----------------
#define SCH 32
__global__ void __launch_bounds__(256) scan_kernel(
    const float* __restrict__ xbc0, const float* __restrict__ xbc1,
    const float* __restrict__ dtp0, const float* __restrict__ dtp1,
    const float* __restrict__ dAp0, const float* __restrict__ dAp1,
    const float* __restrict__ Dp0, const float* __restrict__ Dp1,
    float* __restrict__ y0, float* __restrict__ y1)
{
    const int z = blockIdx.z;
    const float* xbc = z ? xbc1 : xbc0;
    const float* dt = z ? dtp1 : dtp0;
    const float* dA = z ? dAp1 : dAp0;
    const float* Dp = z ? Dp1 : Dp0;
    float* y = z ? y1 : y0;

    const int head = blockIdx.y;
    const int ps   = blockIdx.x;
    const int tid  = threadIdx.x;
    const int pl   = tid >> 3;
    const int n0   = (tid & 7) * 8;
    const float Dh = Dp[head];
    const int xoff = head * HD + ps * 32;

    // B and C are adjacent in xbc: one contiguous 128-float row per timestep.
    __shared__ float sBC[2][SCH][128];
    __shared__ float sx[2][SCH][32];
    __shared__ float sdt[2][SCH];
    __shared__ float sdA[2][SCH];

    float h[8];
#pragma unroll
    for (int j = 0; j < 8; j++) h[j] = 0.f;

    auto stage = [&](int s, int t0) {
        // BC: SCH rows x 32 granules (16B)
#pragma unroll
        for (int it = 0; it < SCH / 8; it++) {
            const int q = tid + it * 256;
            const int r = q >> 5, c = (q & 31) * 4;
            cpa16(smem_u32(&sBC[s][r][c]), &xbc[(size_t)(t0 + r) * CONVDIM + OFF_B + c]);
        }
        // x: SCH rows x 8 granules
        {
            const int r = tid >> 3, c = (tid & 7) * 4;
            cpa16(smem_u32(&sx[s][r][c]), &xbc[(size_t)(t0 + r) * CONVDIM + xoff + c]);
        }
        // dt / dA scalars
        if (tid >= 192 && tid < 192 + SCH)
            cpa4(smem_u32(&sdt[s][tid - 192]), &dt[(size_t)(t0 + tid - 192) * NH + head]);
        if (tid >= 224)
            cpa4(smem_u32(&sdA[s][tid - 224]), &dA[(size_t)(t0 + tid - 224) * NH + head]);
    };

    const int NCH = L / SCH;
    stage(0, 0);
    CP_COMMIT;

    for (int i = 0; i < NCH; i++) {
        const int s = i & 1;
        if (i + 1 < NCH) { stage(s ^ 1, (i + 1) * SCH); CP_COMMIT; CP_WAIT(1); }
        else             { CP_WAIT(0); }
        __syncthreads();
        const int t0 = i * SCH;
        for (int tt = 0; tt < SCH; tt++) {
            const float dtv = sdt[s][tt];
            const float dAv = sdA[s][tt];
            const float xp  = sx[s][tt][pl];
            const float dtx = dtv * xp;
            float b[8], c[8];
            *reinterpret_cast<float4*>(b)     = *reinterpret_cast<const float4*>(&sBC[s][tt][n0]);
            *reinterpret_cast<float4*>(b + 4) = *reinterpret_cast<const float4*>(&sBC[s][tt][n0 + 4]);
            *reinterpret_cast<float4*>(c)     = *reinterpret_cast<const float4*>(&sBC[s][tt][64 + n0]);
            *reinterpret_cast<float4*>(c + 4) = *reinterpret_cast<const float4*>(&sBC[s][tt][64 + n0 + 4]);
            float a0 = 0.f, a1 = 0.f;
#pragma unroll
            for (int j = 0; j < 4; j++) {
                h[j] = fmaf(h[j], dAv, dtx * b[j]);
                a0   = fmaf(h[j], c[j], a0);
            }
#pragma unroll
            for (int j = 4; j < 8; j++) {
                h[j] = fmaf(h[j], dAv, dtx * b[j]);
                a1   = fmaf(h[j], c[j], a1);
            }
            float acc = a0 + a1;
            acc += __shfl_down_sync(0xffffffffu, acc, 4, 8);
            acc += __shfl_down_sync(0xffffffffu, acc, 2, 8);
            acc += __shfl_down_sync(0xffffffffu, acc, 1, 8);
            if ((tid & 7) == 0)
                y[(size_t)(t0 + tt) * DINNER + head * HD + ps * 32 + pl] = fmaf(Dh, xp, acc);
        }
        __syncthreads();
    }
}

// ---------------- gate + RMSNorm -> f16, z-batched ----------------
__global__ void __launch_bounds__(256) gatenorm_kernel(
    const float* __restrict__ zx0, const float* __restrict__ zx1,
    const float* __restrict__ nw0, const float* __restrict__ nw1,
    const float* __restrict__ y0, const float* __restrict__ y1,
    __half* __restrict__ yh0, __half* __restrict__ yh1)
{
    const int z = blockIdx.y;
    const float* zx = z ? zx1 : zx0;
    const float* norm_w = z ? nw1 : nw0;
    const float* y = z ? y1 : y0;
    __half* yh = z ? yh1 : yh0;

    const int t = blockIdx.x;
    const int tid = threadIdx.x;
    __shared__ float red[8];

    float vals[8];
    float local = 0.f;
#pragma unroll
    for (int i = 0; i < 8; i++) {
        const int c = tid + i * 256;
        const float zz = zx[(size_t)t * DINPROJ + OFF_Z + c];
        const float yv = y[(size_t)t * DINNER + c];
        const float yg = yv * siluf(zz);
        vals[i] = yg;
        local = fmaf(yg, yg, local);
    }
#pragma unroll
    for (int o = 16; o > 0; o >>= 1)
        local += __shfl_down_sync(0xffffffffu, local, o);
    if ((tid & 31) == 0) red[tid >> 5] = local;
    __syncthreads();
    if (tid < 8) {
        float v = red[tid];
#pragma unroll
        for (int o = 4; o > 0; o >>= 1)
            v += __shfl_down_sync(0xffu, v, o, 8);
        if (tid == 0) red[0] = v;
    }
    __syncthreads();
    const float scale = rsqrtf(red[0] * (1.f / (float)DINNER) + EPSF);
#pragma unroll
    for (int i = 0; i < 8; i++) {
        const int c = tid + i * 256;
        yh[(size_t)t * DINNER + c] = __float2half(vals[i] * scale * norm_w[c]);
    }
}

// ---------------- launch ----------------
extern "C" void kernel_launch(void* const* d_in, const int* in_sizes, int n_in,
                              void* d_out, int out_size)
{
    const float* u        = (const float*)d_in[0];
    const float* W_in_f   = (const float*)d_in[1];
    const float* W_in_b   = (const float*)d_in[2];
    const float* conv_w_f = (const float*)d_in[3];
    const float* conv_b_f = (const float*)d_in[4];
    const float* conv_w_b = (const float*)d_in[5];
    const float* conv_b_b = (const float*)d_in[6];
    const float* dtb_f    = (const float*)d_in[7];
    const float* dtb_b    = (const float*)d_in[8];
    const float* Alog_f   = (const float*)d_in[9];
    const float* Alog_b   = (const float*)d_in[10];
    const float* D_f      = (const float*)d_in[11];
    const float* D_b      = (const float*)d_in[12];
    const float* nw_f     = (const float*)d_in[13];
    const float* nw_b     = (const float*)d_in[14];
    const float* W_out_f  = (const float*)d_in[15];
    const float* W_out_b  = (const float*)d_in[16];
    const float* W_out    = (const float*)d_in[17];
    float* out = (float*)d_out;

    float *zx_f, *zx_b, *xbc_f, *xbc_b, *dt_f, *dt_b, *dA_f, *dA_b, *y_f, *y_b;
    cudaGetSymbolAddress((void**)&zx_f,  g_zx_f);
    cudaGetSymbolAddress((void**)&zx_b,  g_zx_b);
    cudaGetSymbolAddress((void**)&xbc_f, g_xbc_f);
    cudaGetSymbolAddress((void**)&xbc_b, g_xbc_b);
    cudaGetSymbolAddress((void**)&dt_f,  g_dt_f);
    cudaGetSymbolAddress((void**)&dt_b,  g_dt_b);
    cudaGetSymbolAddress((void**)&dA_f,  g_dA_f);
    cudaGetSymbolAddress((void**)&dA_b,  g_dA_b);
    cudaGetSymbolAddress((void**)&y_f,   g_y_f);
    cudaGetSymbolAddress((void**)&y_b,   g_y_b);

    __half *u16, *win16_f, *win16_b, *wout16_f, *wout16_b, *wfin16, *y16_f, *y16_b, *f16;
    cudaGetSymbolAddress((void**)&u16,      g_u16);
    cudaGetSymbolAddress((void**)&win16_f,  g_win16_f);
    cudaGetSymbolAddress((void**)&win16_b,  g_win16_b);
    cudaGetSymbolAddress((void**)&wout16_f, g_wout16_f);
    cudaGetSymbolAddress((void**)&wout16_b, g_wout16_b);
    cudaGetSymbolAddress((void**)&wfin16,   g_wfin16);
    cudaGetSymbolAddress((void**)&y16_f,    g_y16_f);
    cudaGetSymbolAddress((void**)&y16_b,    g_y16_b);
    cudaGetSymbolAddress((void**)&f16,      g_f16);

    constexpr int SMEM_128 = 3 * (16384 + 128 * 128);   // 98304
    constexpr int SMEM_64  = 3 * (16384 + 64 * 128);    // 73728
    cudaFuncSetAttribute(gemm_k<128, 0>, cudaFuncAttributeMaxDynamicSharedMemorySize, SMEM_128);
    cudaFuncSetAttribute(gemm_k<64, 0>,  cudaFuncAttributeMaxDynamicSharedMemorySize, SMEM_64);
    cudaFuncSetAttribute(gemm_k<64, 1>,  cudaFuncAttributeMaxDynamicSharedMemorySize, SMEM_64);

    // zero the win16 pad rows (memset nodes, not kernel launches)
    cudaMemsetAsync(win16_f + (size_t)DINPROJ * DMODEL, 0,
                    (size_t)(DINPROJ_PAD - DINPROJ) * DMODEL * sizeof(__half));
    cudaMemsetAsync(win16_b + (size_t)DINPROJ * DMODEL, 0,
                    (size_t)(DINPROJ_PAD - DINPROJ) * DMODEL * sizeof(__half));

    // idx0: u convert (flat)
    cvtf_kernel<<<dim3(512, 1, 1), 256>>>(u, u, u16, u16, (size_t)L * DMODEL);
    // idx1: in_proj weight converts (flat, f+b)
    cvtf_kernel<<<dim3(1024, 1, 2), 256>>>(W_in_f, W_in_b, win16_f, win16_b,
                                           (size_t)DINPROJ * DMODEL);
    // idx2: out_proj + final weight converts (flat, z=3)
    cvtf3_kernel<<<dim3(1024, 1, 3), 256>>>(W_out_f, W_out_b, W_out,
                                            wout16_f, wout16_b, wfin16,
                                            (size_t)DMODEL * DINNER);
    // idx3 (ncu capture slot): in_proj GEMM, f+b batched (dir-b rows flipped)
    {
        GArgs ga = {};
        ga.A0 = u16; ga.A1 = u16;
        ga.W0 = win16_f; ga.W1 = win16_b;
        ga.C0 = zx_f; ga.C1 = zx_b;
        ga.N = DINPROJ; ga.K = DMODEL; ga.flip0 = 0; ga.flip1 = 1;
        dim3 grid(DINPROJ_PAD / 128, 8, 2);
        gemm_k<128, 0><<<grid, 256, SMEM_128>>>(ga);
    }
    // idx4: conv + silu + dt/dA tail (f+b)
    conv_dt_kernel<<<dim3((L * CONVDIM + L * NH + 255) / 256, 2), 256>>>(
        zx_f, zx_b, conv_w_f, conv_w_b, conv_b_f, conv_b_b,
        dtb_f, dtb_b, Alog_f, Alog_b,
        xbc_f, xbc_b, dt_f, dt_b, dA_f, dA_b);
    // idx5: scan (f+b), cp.async double-buffered
    scan_kernel<<<dim3(2, NH, 2), 256>>>(
        xbc_f, xbc_b, dt_f, dt_b, dA_f, dA_b, D_f, D_b, y_f, y_b);
    // idx6: gate + rmsnorm -> f16 (f+b)
    gatenorm_kernel<<<dim3(L, 2), 256>>>(
        zx_f, zx_b, nw_f, nw_b, y_f, y_b, y16_f, y16_b);
    // idx7: out_proj GEMM (f+b batched, fused silu -> f16 concat epilogue)
    {
        GArgs ga = {};
        ga.A0 = y16_f; ga.A1 = y16_b;
        ga.W0 = wout16_f; ga.W1 = wout16_b;
        ga.E = f16;
        ga.N = DMODEL; ga.K = DINNER; ga.flip0 = 0; ga.flip1 = 1;
        dim3 grid(DMODEL / 64, 8, 2);
        gemm_k<64, 1><<<grid, 256, SMEM_64>>>(ga);
    }
    // idx8: final GEMM: f16concat @ W_out^T -> out
    {
        GArgs ga = {};
        ga.A0 = f16; ga.W0 = wfin16; ga.C0 = out;
        ga.N = DMODEL; ga.K = 2 * DMODEL; ga.flip0 = 0;
        dim3 grid(DMODEL / 64, 8, 1);
        gemm_k<64, 0><<<grid, 256, SMEM_64>>>(ga);
    }
}

// round 15
// speedup vs baseline: 1.0708x; 1.0708x over previous
#include <cuda_runtime.h>
#include <cuda_fp16.h>
#include <math.h>
#include <stdint.h>

// ---------------- problem constants ----------------
#define L        1024
#define DMODEL   1024
#define DINNER   2048
#define NH       32
#define HD       64
#define CONVDIM  2176           // DINNER + 2*G*N
#define DINPROJ  4256           // 2*DINNER + 2*G*N + NH
#define DINPROJ_PAD 4352        // 34 * 128
#define OFF_Z    0
#define OFF_XBC  2048
#define OFF_B    2048
#define OFF_DT   4224
#define EPSF     1e-5f

// ---------------- scratch (device globals; no allocs allowed) ----------------
__device__ float g_zx_f[L * DINPROJ];
__device__ float g_zx_b[L * DINPROJ];
__device__ float g_xbc_f[L * CONVDIM];
__device__ float g_xbc_b[L * CONVDIM];
__device__ float g_dt_f[L * NH];
__device__ float g_dt_b[L * NH];
__device__ float g_dA_f[L * NH];
__device__ float g_dA_b[L * NH];
__device__ float g_y_f[L * DINNER];
__device__ float g_y_b[L * DINNER];

// fp16 operands
__device__ __half g_u16[L * DMODEL];
__device__ __half g_win16_f[DINPROJ_PAD * DMODEL];
__device__ __half g_win16_b[DINPROJ_PAD * DMODEL];
__device__ __half g_wout16_f[DMODEL * DINNER];
__device__ __half g_wout16_b[DMODEL * DINNER];
__device__ __half g_wfin16[DMODEL * (2 * DMODEL)];
__device__ __half g_y16_f[L * DINNER];
__device__ __half g_y16_b[L * DINNER];
__device__ __half g_f16[L * (2 * DMODEL)];

__device__ __forceinline__ float siluf(float x) { return x / (1.f + expf(-x)); }

// ---------------- PTX helpers ----------------
__device__ __forceinline__ uint32_t smem_u32(const void* p) {
    uint32_t a;
    asm("{ .reg .u64 t; cvta.to.shared.u64 t, %1; cvt.u32.u64 %0, t; }" : "=r"(a) : "l"(p));
    return a;
}
__device__ __forceinline__ void cpa16(uint32_t dst, const void* src) {
    asm volatile("cp.async.cg.shared.global [%0], [%1], 16;" :: "r"(dst), "l"(src));
}
#define CP_COMMIT asm volatile("cp.async.commit_group;" ::: "memory")
#define CP_WAIT(n) asm volatile("cp.async.wait_group %0;" :: "n"(n) : "memory")

__device__ __forceinline__ void ldm_x4(uint32_t a[4], uint32_t addr) {
    asm volatile("ldmatrix.sync.aligned.m8n8.x4.shared.b16 {%0,%1,%2,%3}, [%4];"
        : "=r"(a[0]), "=r"(a[1]), "=r"(a[2]), "=r"(a[3]) : "r"(addr));
}
__device__ __forceinline__ void mma_f16(float c[4], const uint32_t a[4], uint32_t b0, uint32_t b1) {
    asm volatile("mma.sync.aligned.m16n8k16.row.col.f32.f16.f16.f32 "
        "{%0,%1,%2,%3}, {%4,%5,%6,%7}, {%8,%9}, {%0,%1,%2,%3};"
        : "+f"(c[0]), "+f"(c[1]), "+f"(c[2]), "+f"(c[3])
        : "r"(a[0]), "r"(a[1]), "r"(a[2]), "r"(a[3]), "r"(b0), "r"(b1));
}
__device__ __forceinline__ uint32_t pack_h2(__half a, __half b) {
    __half2 t(a, b);
    return *reinterpret_cast<uint32_t*>(&t);
}

// ---------------- GEMM argument bundle ----------------
struct GArgs {
    const __half *A0, *A1, *W0, *W1;
    float *C0, *C1;        // EPI=0
    __half *E;             // EPI=1 (silu -> f16 concat buffer, row stride 2048)
    int N, K;
    int flip0, flip1;      // epilogue row flips per z
};

// ================= Unified GEMM: BM=128, BK=64, 256 threads / 8 warps, 2 CTAs/SM =================
template <int BN, int EPI>
__global__ void __launch_bounds__(256, 2) gemm_k(GArgs a)
{
    constexpr int WN = BN / 2;
    constexpr int NT = WN / 8;
    constexpr int NG = WN / 16;
    constexpr int STAGE = 16384 + BN * 128;
    extern __shared__ __align__(128) char smem[];
    const uint32_t sb = smem_u32(smem);
    const int tid = threadIdx.x;
    const int lane = tid & 31;
    const int wid = tid >> 5;
    const int z = blockIdx.z;
    const int bm = blockIdx.y * 128;
    const int bn = blockIdx.x * BN;
    const int m0w = (wid >> 1) * 32;
    const int n0w = (wid & 1) * WN;
    const int N = a.N, K = a.K;

    const __half* A = z ? a.A1 : a.A0;
    const __half* W = z ? a.W1 : a.W0;
    const bool flip = z ? (a.flip1 != 0) : (a.flip0 != 0);

    float acc[2][NT][4];
#pragma unroll
    for (int i = 0; i < 2; i++)
#pragma unroll
        for (int j = 0; j < NT; j++)
#pragma unroll
            for (int q = 0; q < 4; q++) acc[i][j][q] = 0.f;

    auto load_stage = [&](int s, int k0) {
        const uint32_t base = sb + s * STAGE;
#pragma unroll
        for (int it = 0; it < 4; it++) {
            const int q = tid + it * 256;
            const int r = q >> 3, c = q & 7;
            const uint32_t sw = r * 128 + ((uint32_t)(c ^ (r & 7)) << 4);
            cpa16(base + sw, A + (size_t)(bm + r) * K + k0 + c * 8);
        }
#pragma unroll
        for (int it = 0; it < BN / 32; it++) {
            const int q = tid + it * 256;
            const int r = q >> 3, c = q & 7;
            const uint32_t sw = r * 128 + ((uint32_t)(c ^ (r & 7)) << 4);
            cpa16(base + 16384 + sw, W + (size_t)(bn + r) * K + k0 + c * 8);
        }
    };

    const int NC = K >> 6;
    load_stage(0, 0);
    CP_COMMIT;
    load_stage(1, 64);
    CP_COMMIT;

    int cs = 0;
    for (int i = 0; i < NC; i++) {
        if (i + 1 < NC) { CP_WAIT(1); } else { CP_WAIT(0); }
        __syncthreads();
        if (i + 2 < NC) {
            int ps = cs + 2; if (ps >= 3) ps -= 3;
            load_stage(ps, (i + 2) << 6);
            CP_COMMIT;
        }
        const uint32_t base = sb + cs * STAGE;
#pragma unroll
        for (int ks = 0; ks < 4; ks++) {
            const int c0 = ks * 2;
            uint32_t af[2][4];
#pragma unroll
            for (int ii = 0; ii < 2; ii++) {
                const int row = m0w + ii * 16 + (lane & 15);
                const int ch = c0 + (lane >> 4);
                ldm_x4(af[ii], base + row * 128 + (uint32_t)((ch ^ (row & 7)) << 4));
            }
#pragma unroll
            for (int j = 0; j < NG; j++) {
                uint32_t bw[4];
                const int row = n0w + j * 16 + ((lane >> 4) << 3) + (lane & 7);
                const int ch = c0 + ((lane >> 3) & 1);
                ldm_x4(bw, base + 16384 + row * 128 + (uint32_t)((ch ^ (row & 7)) << 4));
                mma_f16(acc[0][2 * j],     af[0], bw[0], bw[1]);
                mma_f16(acc[0][2 * j + 1], af[0], bw[2], bw[3]);
                mma_f16(acc[1][2 * j],     af[1], bw[0], bw[1]);
                mma_f16(acc[1][2 * j + 1], af[1], bw[2], bw[3]);
            }
        }
        cs++; if (cs >= 3) cs = 0;
    }

    if (EPI == 0) {
        float* C = z ? a.C1 : a.C0;
#pragma unroll
        for (int ii = 0; ii < 2; ii++) {
            const int gr = bm + m0w + ii * 16 + (lane >> 2);
            const int r0 = flip ? (1023 - gr) : gr;
            const int r1 = flip ? (1023 - (gr + 8)) : (gr + 8);
#pragma unroll
            for (int jj = 0; jj < NT; jj++) {
                const int gc = bn + n0w + jj * 8 + (lane & 3) * 2;
                if (gc < N) {
                    *reinterpret_cast<float2*>(&C[(size_t)r0 * N + gc]) = make_float2(acc[ii][jj][0], acc[ii][jj][1]);
                    *reinterpret_cast<float2*>(&C[(size_t)r1 * N + gc]) = make_float2(acc[ii][jj][2], acc[ii][jj][3]);
                }
            }
        }
    } else {
        const int colOff = z * 1024;
#pragma unroll
        for (int ii = 0; ii < 2; ii++) {
            const int gr = bm + m0w + ii * 16 + (lane >> 2);
            const int r0 = flip ? (1023 - gr) : gr;
            const int r1 = flip ? (1023 - (gr + 8)) : (gr + 8);
#pragma unroll
            for (int jj = 0; jj < NT; jj++) {
                const int gc = colOff + bn + n0w + jj * 8 + (lane & 3) * 2;
                const float v0 = siluf(acc[ii][jj][0]);
                const float v1 = siluf(acc[ii][jj][1]);
                const float v2 = siluf(acc[ii][jj][2]);
                const float v3 = siluf(acc[ii][jj][3]);
                *reinterpret_cast<uint32_t*>(&a.E[(size_t)r0 * 2048 + gc]) = pack_h2(__float2half(v0), __float2half(v1));
                *reinterpret_cast<uint32_t*>(&a.E[(size_t)r1 * 2048 + gc]) = pack_h2(__float2half(v2), __float2half(v3));
            }
        }
    }
}

// ---------------- f32 -> f16 convert (+ zero pad rows), 2-way z ----------------
__global__ void cvt_kernel(const float* __restrict__ s0, const float* __restrict__ s1,
                           __half* __restrict__ d0, __half* __restrict__ d1,
                           int rows, int K)
{
    const float* s = blockIdx.z ? s1 : s0;
    __half* d = blockIdx.z ? d1 : d0;
    const int r = blockIdx.y;
    const int c = (blockIdx.x * 256 + threadIdx.x) * 4;
    if (c >= K) return;
    float4 v = make_float4(0.f, 0.f, 0.f, 0.f);
    if (r < rows) v = *reinterpret_cast<const float4*>(&s[(size_t)r * K + c]);
    *reinterpret_cast<uint2*>(&d[(size_t)r * K + c]) =
        make_uint2(pack_h2(__float2half(v.x), __float2half(v.y)),
                   pack_h2(__float2half(v.z), __float2half(v.w)));
}

// ---------------- f32 -> f16 convert, 3-way z (same shape) ----------------
__global__ void cvt3_kernel(const float* __restrict__ s0, const float* __restrict__ s1,
                            const float* __restrict__ s2,
                            __half* __restrict__ d0, __half* __restrict__ d1,
                            __half* __restrict__ d2, int K)
{
    const float* s = (blockIdx.z == 0) ? s0 : (blockIdx.z == 1) ? s1 : s2;
    __half* d = (blockIdx.z == 0) ? d0 : (blockIdx.z == 1) ? d1 : d2;
    const int r = blockIdx.y;
    const int c = (blockIdx.x * 256 + threadIdx.x) * 4;
    if (c >= K) return;
    float4 v = *reinterpret_cast<const float4*>(&s[(size_t)r * K + c]);
    *reinterpret_cast<uint2*>(&d[(size_t)r * K + c]) =
        make_uint2(pack_h2(__float2half(v.x), __float2half(v.y)),
                   pack_h2(__float2half(v.z), __float2half(v.w)));
}

// ---------------- conv (4 t per thread) + SiLU + dt/dA tail, z-batched ----------------
#define CONV_WORK (L / 4 * CONVDIM)
__global__ void conv_dt_kernel(const float* __restrict__ zx0, const float* __restrict__ zx1,
                               const float* __restrict__ cw0, const float* __restrict__ cw1,
                               const float* __restrict__ cb0, const float* __restrict__ cb1,
                               const float* __restrict__ db0, const float* __restrict__ db1,
                               const float* __restrict__ al0, const float* __restrict__ al1,
                               float* __restrict__ out0, float* __restrict__ out1,
                               float* __restrict__ dt0, float* __restrict__ dt1,
                               float* __restrict__ dA0, float* __restrict__ dA1)
{
    const int z = blockIdx.y;
    const float* zx = z ? zx1 : zx0;
    const int idx = blockIdx.x * blockDim.x + threadIdx.x;
    if (idx < CONV_WORK) {
        const float* cw = z ? cw1 : cw0;
        const float* cb = z ? cb1 : cb0;
        float* out = z ? out1 : out0;
        const int t4 = idx / CONVDIM;
        const int c = idx - t4 * CONVDIM;
        const int t0 = t4 * 4;
        // load zx[t0-3 .. t0+3][col] (guard below 0)
        float v[7];
#pragma unroll
        for (int k = 0; k < 7; k++) {
            const int tt = t0 - 3 + k;
            v[k] = (tt >= 0) ? zx[(size_t)tt * DINPROJ + OFF_XBC + c] : 0.f;
        }
        const float w0 = cw[c * 4 + 0], w1 = cw[c * 4 + 1], w2 = cw[c * 4 + 2], w3 = cw[c * 4 + 3];
        const float bb = cb[c];
#pragma unroll
        for (int i = 0; i < 4; i++) {
            float acc = bb;
            acc = fmaf(v[i + 0], w0, acc);
            acc = fmaf(v[i + 1], w1, acc);
            acc = fmaf(v[i + 2], w2, acc);
            acc = fmaf(v[i + 3], w3, acc);
            out[(size_t)(t0 + i) * CONVDIM + c] = siluf(acc);
        }
    } else {
        const int j = idx - CONV_WORK;
        if (j < L * NH) {
            const float* dt_bias = z ? db1 : db0;
            const float* A_log = z ? al1 : al0;
            float* dt_out = z ? dt1 : dt0;
            float* dA_out = z ? dA1 : dA0;
            const int h = j & (NH - 1);
            const float v = zx[(size_t)(j >> 5) * DINPROJ + OFF_DT + h] + dt_bias[h];
            const float sp = (v > 20.f) ? v : log1pf(expf(v));
            dt_out[j] = sp;
            dA_out[j] = expf(sp * (-expf(A_log[h])));
        }
    }
}

// ---------------- SSM scan, z-batched, tt loop unrolled x4 ----------------
#define SCHUNK 16
__global__ void __launch_bounds__(256) scan_kernel(
    const float* __restrict__ xbc0, const float* __restrict__ xbc1,
    const float* __restrict__ dtp0, const float* __restrict__ dtp1,
    const float* __restrict__ dAp0, const float* __restrict__ dAp1,
    const float* __restrict__ Dp0, const float* __restrict__ Dp1,
    float* __restrict__ y0, float* __restrict__ y1)
{
    const int z = blockIdx.z;
    const float* xbc = z ? xbc1 : xbc0;
    const float* dt = z ? dtp1 : dtp0;
    const float* dA = z ? dAp1 : dAp0;
    const float* Dp = z ? Dp1 : Dp0;
    float* y = z ? y1 : y0;

    const int head = blockIdx.y;
    const int ps   = blockIdx.x;
    const int tid  = threadIdx.x;
    const int pl   = tid >> 3;
    const int n0   = (tid & 7) * 8;
    const float Dh = Dp[head];
    const int xoff = head * HD + ps * 32;

    __shared__ float sB[SCHUNK][64];
    __shared__ float sC[SCHUNK][64];
    __shared__ float sx[SCHUNK][32];
    __shared__ float sdt[SCHUNK];
    __shared__ float sdA[SCHUNK];

    float h[8];
#pragma unroll
    for (int j = 0; j < 8; j++) h[j] = 0.f;

    for (int t0 = 0; t0 < L; t0 += SCHUNK) {
        {
            const int lt = tid >> 4;
            const int lc = (tid & 15) * 4;
            const int t  = t0 + lt;
            *reinterpret_cast<float4*>(&sB[lt][lc]) =
                *reinterpret_cast<const float4*>(&xbc[(size_t)t * CONVDIM + OFF_B + lc]);
            *reinterpret_cast<float4*>(&sC[lt][lc]) =
                *reinterpret_cast<const float4*>(&xbc[(size_t)t * CONVDIM + OFF_B + 64 + lc]);
            if (lc < 32)
                *reinterpret_cast<float4*>(&sx[lt][lc]) =
                    *reinterpret_cast<const float4*>(&xbc[(size_t)t * CONVDIM + xoff + lc]);
            if (tid < SCHUNK) {
                sdt[tid] = dt[(size_t)(t0 + tid) * NH + head];
                sdA[tid] = dA[(size_t)(t0 + tid) * NH + head];
            }
        }
        __syncthreads();

#pragma unroll 4
        for (int tt = 0; tt < SCHUNK; tt++) {
            const float dtv = sdt[tt];
            const float dAv = sdA[tt];
            const float xp  = sx[tt][pl];
            const float dtx = dtv * xp;
            float b[8], c[8];
            *reinterpret_cast<float4*>(b)     = *reinterpret_cast<const float4*>(&sB[tt][n0]);
            *reinterpret_cast<float4*>(b + 4) = *reinterpret_cast<const float4*>(&sB[tt][n0 + 4]);
            *reinterpret_cast<float4*>(c)     = *reinterpret_cast<const float4*>(&sC[tt][n0]);
            *reinterpret_cast<float4*>(c + 4) = *reinterpret_cast<const float4*>(&sC[tt][n0 + 4]);
            float a0 = 0.f, a1 = 0.f;
#pragma unroll
            for (int j = 0; j < 4; j++) {
                h[j] = fmaf(h[j], dAv, dtx * b[j]);
                a0   = fmaf(h[j], c[j], a0);
            }
#pragma unroll
            for (int j = 4; j < 8; j++) {
                h[j] = fmaf(h[j], dAv, dtx * b[j]);
                a1   = fmaf(h[j], c[j], a1);
            }
            float acc = a0 + a1;
            acc += __shfl_down_sync(0xffffffffu, acc, 4, 8);
            acc += __shfl_down_sync(0xffffffffu, acc, 2, 8);
            acc += __shfl_down_sync(0xffffffffu, acc, 1, 8);
            if ((tid & 7) == 0)
                y[(size_t)(t0 + tt) * DINNER + head * HD + ps * 32 + pl] = fmaf(Dh, xp, acc);
        }
        __syncthreads();
    }
}

// ---------------- gate + RMSNorm -> f16, z-batched ----------------
__global__ void __launch_bounds__(256) gatenorm_kernel(
    const float* __restrict__ zx0, const float* __restrict__ zx1,
    const float* __restrict__ nw0, const float* __restrict__ nw1,
    const float* __restrict__ y0, const float* __restrict__ y1,
    __half* __restrict__ yh0, __half* __restrict__ yh1)
{
    const int z = blockIdx.y;
    const float* zx = z ? zx1 : zx0;
    const float* norm_w = z ? nw1 : nw0;
    const float* y = z ? y1 : y0;
    __half* yh = z ? yh1 : yh0;

    const int t = blockIdx.x;
    const int tid = threadIdx.x;
    __shared__ float red[8];

    float vals[8];
    float local = 0.f;
#pragma unroll
    for (int i = 0; i < 8; i++) {
        const int c = tid + i * 256;
        const float zz = zx[(size_t)t * DINPROJ + OFF_Z + c];
        const float yv = y[(size_t)t * DINNER + c];
        const float yg = yv * siluf(zz);
        vals[i] = yg;
        local = fmaf(yg, yg, local);
    }
#pragma unroll
    for (int o = 16; o > 0; o >>= 1)
        local += __shfl_down_sync(0xffffffffu, local, o);
    if ((tid & 31) == 0) red[tid >> 5] = local;
    __syncthreads();
    if (tid < 8) {
        float v = red[tid];
#pragma unroll
        for (int o = 4; o > 0; o >>= 1)
            v += __shfl_down_sync(0xffu, v, o, 8);
        if (tid == 0) red[0] = v;
    }
    __syncthreads();
    const float scale = rsqrtf(red[0] * (1.f / (float)DINNER) + EPSF);
#pragma unroll
    for (int i = 0; i < 8; i++) {
        const int c = tid + i * 256;
        yh[(size_t)t * DINNER + c] = __float2half(vals[i] * scale * norm_w[c]);
    }
}

// ---------------- launch ----------------
extern "C" void kernel_launch(void* const* d_in, const int* in_sizes, int n_in,
                              void* d_out, int out_size)
{
    const float* u        = (const float*)d_in[0];
    const float* W_in_f   = (const float*)d_in[1];
    const float* W_in_b   = (const float*)d_in[2];
    const float* conv_w_f = (const float*)d_in[3];
    const float* conv_b_f = (const float*)d_in[4];
    const float* conv_w_b = (const float*)d_in[5];
    const float* conv_b_b = (const float*)d_in[6];
    const float* dtb_f    = (const float*)d_in[7];
    const float* dtb_b    = (const float*)d_in[8];
    const float* Alog_f   = (const float*)d_in[9];
    const float* Alog_b   = (const float*)d_in[10];
    const float* D_f      = (const float*)d_in[11];
    const float* D_b      = (const float*)d_in[12];
    const float* nw_f     = (const float*)d_in[13];
    const float* nw_b     = (const float*)d_in[14];
    const float* W_out_f  = (const float*)d_in[15];
    const float* W_out_b  = (const float*)d_in[16];
    const float* W_out    = (const float*)d_in[17];
    float* out = (float*)d_out;

    float *zx_f, *zx_b, *xbc_f, *xbc_b, *dt_f, *dt_b, *dA_f, *dA_b, *y_f, *y_b;
    cudaGetSymbolAddress((void**)&zx_f,  g_zx_f);
    cudaGetSymbolAddress((void**)&zx_b,  g_zx_b);
    cudaGetSymbolAddress((void**)&xbc_f, g_xbc_f);
    cudaGetSymbolAddress((void**)&xbc_b, g_xbc_b);
    cudaGetSymbolAddress((void**)&dt_f,  g_dt_f);
    cudaGetSymbolAddress((void**)&dt_b,  g_dt_b);
    cudaGetSymbolAddress((void**)&dA_f,  g_dA_f);
    cudaGetSymbolAddress((void**)&dA_b,  g_dA_b);
    cudaGetSymbolAddress((void**)&y_f,   g_y_f);
    cudaGetSymbolAddress((void**)&y_b,   g_y_b);

    __half *u16, *win16_f, *win16_b, *wout16_f, *wout16_b, *wfin16, *y16_f, *y16_b, *f16;
    cudaGetSymbolAddress((void**)&u16,      g_u16);
    cudaGetSymbolAddress((void**)&win16_f,  g_win16_f);
    cudaGetSymbolAddress((void**)&win16_b,  g_win16_b);
    cudaGetSymbolAddress((void**)&wout16_f, g_wout16_f);
    cudaGetSymbolAddress((void**)&wout16_b, g_wout16_b);
    cudaGetSymbolAddress((void**)&wfin16,   g_wfin16);
    cudaGetSymbolAddress((void**)&y16_f,    g_y16_f);
    cudaGetSymbolAddress((void**)&y16_b,    g_y16_b);
    cudaGetSymbolAddress((void**)&f16,      g_f16);

    constexpr int SMEM_128 = 3 * (16384 + 128 * 128);   // 98304
    constexpr int SMEM_64  = 3 * (16384 + 64 * 128);    // 73728
    cudaFuncSetAttribute(gemm_k<128, 0>, cudaFuncAttributeMaxDynamicSharedMemorySize, SMEM_128);
    cudaFuncSetAttribute(gemm_k<64, 0>,  cudaFuncAttributeMaxDynamicSharedMemorySize, SMEM_64);
    cudaFuncSetAttribute(gemm_k<64, 1>,  cudaFuncAttributeMaxDynamicSharedMemorySize, SMEM_64);

    // idx0: u convert
    cvt_kernel<<<dim3(1, L, 1), 256>>>(u, u, u16, u16, L, DMODEL);
    // idx1: in_proj weight converts (f+b batched, pads rows to DINPROJ_PAD)
    cvt_kernel<<<dim3(1, DINPROJ_PAD, 2), 256>>>(W_in_f, W_in_b, win16_f, win16_b, DINPROJ, DMODEL);

    // idx2: in_proj GEMM, f+b batched (dir-b rows flipped)
    {
        GArgs ga = {};
        ga.A0 = u16; ga.A1 = u16;
        ga.W0 = win16_f; ga.W1 = win16_b;
        ga.C0 = zx_f; ga.C1 = zx_b;
        ga.N = DINPROJ; ga.K = DMODEL; ga.flip0 = 0; ga.flip1 = 1;
        dim3 grid(DINPROJ_PAD / 128, 8, 2);
        gemm_k<128, 0><<<grid, 256, SMEM_128>>>(ga);
    }
    // idx3: out_proj + final weight converts (z=3)
    cvt3_kernel<<<dim3(2, DMODEL, 3), 256>>>(W_out_f, W_out_b, W_out,
                                             wout16_f, wout16_b, wfin16, DINNER);
    // idx4: conv (4t/thread) + silu + dt/dA tail (f+b)
    conv_dt_kernel<<<dim3((CONV_WORK + L * NH + 255) / 256, 2), 256>>>(
        zx_f, zx_b, conv_w_f, conv_w_b, conv_b_f, conv_b_b,
        dtb_f, dtb_b, Alog_f, Alog_b,
        xbc_f, xbc_b, dt_f, dt_b, dA_f, dA_b);
    // idx5: scan (f+b)
    scan_kernel<<<dim3(2, NH, 2), 256>>>(
        xbc_f, xbc_b, dt_f, dt_b, dA_f, dA_b, D_f, D_b, y_f, y_b);
    // idx6: gate + rmsnorm -> f16 (f+b)
    gatenorm_kernel<<<dim3(L, 2), 256>>>(
        zx_f, zx_b, nw_f, nw_b, y_f, y_b, y16_f, y16_b);
    // idx7: out_proj GEMM (f+b batched, fused silu -> f16 concat epilogue)
    {
        GArgs ga = {};
        ga.A0 = y16_f; ga.A1 = y16_b;
        ga.W0 = wout16_f; ga.W1 = wout16_b;
        ga.E = f16;
        ga.N = DMODEL; ga.K = DINNER; ga.flip0 = 0; ga.flip1 = 1;
        dim3 grid(DMODEL / 64, 8, 2);
        gemm_k<64, 1><<<grid, 256, SMEM_64>>>(ga);
    }
    // idx8: final GEMM: f16concat @ W_out^T -> out
    {
        GArgs ga = {};
        ga.A0 = f16; ga.W0 = wfin16; ga.C0 = out;
        ga.N = DMODEL; ga.K = 2 * DMODEL; ga.flip0 = 0;
        dim3 grid(DMODEL / 64, 8, 1);
        gemm_k<64, 0><<<grid, 256, SMEM_64>>>(ga);
    }
}